// round 5
// baseline (speedup 1.0000x reference)
#include <cuda_runtime.h>
#include <cstddef>

#define BLOC 16
#define NTHREADS (BLOC * 13)   // 208
#define NB 13
#define DD 16
#define BTOT 32768

typedef unsigned long long u64;

// ---------------- packed constant parameter block ----------------
struct CParams {
    u64 iw2[NB][8];            // pairs (iw[m][2j], iw[m][2j+1])
    u64 w0p[4][DD][8];         // [l][e][jpair]: (w0[l][2j][e], w0[l][2j+1][e])
    u64 w1p[4][DD][8];
    u64 dwp[4][DD][8];
    u64 fc1p[DD][8];
    u64 fc2p[DD][8];
    u64 b02[4][8];
    u64 b12[4][8];
    u64 db2[4][8];
    u64 fc1b2[8];
    u64 fc2b2[8];
    float si[4][NB];
    float ti[4][NB];
    float so[4][NB];
    float to[4][NB];
    float fe[4];
};

__constant__ CParams cP;
__device__ CParams gStage;

// ---------------- pack kernel (repacks weights pair-interleaved) ----------------
__global__ void pack_kernel(
    const float* __restrict__ init_weight,
    const float* __restrict__ eps_param,
    const float* __restrict__ mlp_w0, const float* __restrict__ mlp_b0,
    const float* __restrict__ mlp_w1, const float* __restrict__ mlp_b1,
    const float* __restrict__ big, const float* __restrict__ bib,
    const float* __restrict__ bim, const float* __restrict__ biv,
    const float* __restrict__ bog, const float* __restrict__ bob,
    const float* __restrict__ bom, const float* __restrict__ bov,
    const float* __restrict__ fc1w, const float* __restrict__ fc1b,
    const float* __restrict__ fc2w, const float* __restrict__ fc2b,
    const float* __restrict__ decw, const float* __restrict__ decb)
{
    const int t = threadIdx.x;
    CParams* s = &gStage;

    // iw2: [m][j] pairs, contiguous in d
    for (int idx = t; idx < NB * 8; idx += 256) {
        int m = idx / 8, j = idx % 8;
        float* p = (float*)&s->iw2[m][j];
        p[0] = init_weight[m * DD + 2 * j];
        p[1] = init_weight[m * DD + 2 * j + 1];
    }
    // mlp / dec weights: [l][e][j] = (w[l][2j][e], w[l][2j+1][e])
    for (int idx = t; idx < 4 * DD * 8; idx += 256) {
        int j = idx % 8;
        int e = (idx / 8) % DD;
        int l = idx / (8 * DD);
        {
            float* p = (float*)&s->w0p[l][e][j];
            p[0] = mlp_w0[l * 256 + (2 * j) * DD + e];
            p[1] = mlp_w0[l * 256 + (2 * j + 1) * DD + e];
        }
        {
            float* p = (float*)&s->w1p[l][e][j];
            p[0] = mlp_w1[l * 256 + (2 * j) * DD + e];
            p[1] = mlp_w1[l * 256 + (2 * j + 1) * DD + e];
        }
        {
            float* p = (float*)&s->dwp[l][e][j];
            p[0] = decw[l * 256 + (2 * j) * DD + e];
            p[1] = decw[l * 256 + (2 * j + 1) * DD + e];
        }
    }
    for (int idx = t; idx < DD * 8; idx += 256) {
        int j = idx % 8, e = idx / 8;
        {
            float* p = (float*)&s->fc1p[e][j];
            p[0] = fc1w[(2 * j) * DD + e];
            p[1] = fc1w[(2 * j + 1) * DD + e];
        }
        {
            float* p = (float*)&s->fc2p[e][j];
            p[0] = fc2w[(2 * j) * DD + e];
            p[1] = fc2w[(2 * j + 1) * DD + e];
        }
    }
    if (t < 4 * 8) {
        int l = t / 8, j = t % 8;
        ((float*)&s->b02[l][j])[0] = mlp_b0[l * DD + 2 * j];
        ((float*)&s->b02[l][j])[1] = mlp_b0[l * DD + 2 * j + 1];
        ((float*)&s->b12[l][j])[0] = mlp_b1[l * DD + 2 * j];
        ((float*)&s->b12[l][j])[1] = mlp_b1[l * DD + 2 * j + 1];
        ((float*)&s->db2[l][j])[0] = decb[l * DD + 2 * j];
        ((float*)&s->db2[l][j])[1] = decb[l * DD + 2 * j + 1];
    }
    if (t < 8) {
        ((float*)&s->fc1b2[t])[0] = fc1b[2 * t];
        ((float*)&s->fc1b2[t])[1] = fc1b[2 * t + 1];
        ((float*)&s->fc2b2[t])[0] = fc2b[2 * t];
        ((float*)&s->fc2b2[t])[1] = fc2b[2 * t + 1];
    }
    if (t < 4 * NB) {
        float siv = big[t] * rsqrtf(biv[t] + 1e-5f);
        float sov = bog[t] * rsqrtf(bov[t] + 1e-5f);
        ((float*)s->si)[t] = siv;
        ((float*)s->ti)[t] = bib[t] - bim[t] * siv;
        ((float*)s->so)[t] = sov;
        ((float*)s->to)[t] = bob[t] - bom[t] * sov;
    }
    if (t < 4) s->fe[t] = 1.f + eps_param[t];
}

// ---------------- f32x2 helpers ----------------
__device__ __forceinline__ u64 pack2(float lo, float hi) {
    u64 r; asm("mov.b64 %0, {%1, %2};" : "=l"(r) : "f"(lo), "f"(hi)); return r;
}
__device__ __forceinline__ u64 bcast2(float v) {
    u64 r; asm("mov.b64 %0, {%1, %1};" : "=l"(r) : "f"(v)); return r;
}
__device__ __forceinline__ void unpack2(u64 v, float& lo, float& hi) {
    asm("mov.b64 {%0, %1}, %2;" : "=f"(lo), "=f"(hi) : "l"(v));
}
__device__ __forceinline__ u64 fma2(u64 a, u64 b, u64 c) {
    u64 r; asm("fma.rn.f32x2 %0, %1, %2, %3;" : "=l"(r) : "l"(a), "l"(b), "l"(c)); return r;
}
__device__ __forceinline__ u64 mul2(u64 a, u64 b) {
    u64 r; asm("mul.rn.f32x2 %0, %1, %2;" : "=l"(r) : "l"(a), "l"(b)); return r;
}

__device__ __forceinline__ float leaky(float v) {
    return v >= 0.f ? v : 0.01f * v;
}

// out pairs: out[j] = bias2[j] + sum_e v[e] * wp[e][j]   (packed over d-pairs)
__device__ __forceinline__ void mat16p(const u64 (*__restrict__ wp)[8],
                                       const u64* __restrict__ bp,
                                       const float* __restrict__ v,
                                       u64* __restrict__ out)
{
#pragma unroll
    for (int j = 0; j < 8; j++) out[j] = bp[j];
#pragma unroll
    for (int e = 0; e < DD; e++) {
        u64 ve = bcast2(v[e]);
#pragma unroll
        for (int j = 0; j < 8; j++) out[j] = fma2(ve, wp[e][j], out[j]);
    }
}

// ---------------- main kernel ----------------
struct Smem {
    float adj[BLOC * 676];        // [b_loc][i][n][m]
    float x[BLOC][NB][DD];        // per-b node features (reused for temp)
    float si[4 * NB], ti[4 * NB], so[4 * NB], to[4 * NB];
    float fe[4];
};                                 // ~57.4 KB -> 3 blocks/SM

#define STORE16(dst, src) do {                                  \
    float4* _p = (float4*)(dst);                                \
    _p[0] = make_float4((src)[0],(src)[1],(src)[2],(src)[3]);   \
    _p[1] = make_float4((src)[4],(src)[5],(src)[6],(src)[7]);   \
    _p[2] = make_float4((src)[8],(src)[9],(src)[10],(src)[11]); \
    _p[3] = make_float4((src)[12],(src)[13],(src)[14],(src)[15]);\
} while (0)

// load 16 floats (16B-aligned smem) as 8 u64 pairs
#define LOADP8(dst, src) do {                                   \
    const ulonglong2* _p = (const ulonglong2*)(src);            \
    ulonglong2 _a = _p[0], _b = _p[1], _c = _p[2], _d = _p[3];  \
    (dst)[0]=_a.x; (dst)[1]=_a.y; (dst)[2]=_b.x; (dst)[3]=_b.y; \
    (dst)[4]=_c.x; (dst)[5]=_c.y; (dst)[6]=_d.x; (dst)[7]=_d.y; \
} while (0)

#define STOREP8(dst, src) do {                                  \
    ulonglong2* _p = (ulonglong2*)(dst);                        \
    _p[0] = make_ulonglong2((src)[0], (src)[1]);                \
    _p[1] = make_ulonglong2((src)[2], (src)[3]);                \
    _p[2] = make_ulonglong2((src)[4], (src)[5]);                \
    _p[3] = make_ulonglong2((src)[6], (src)[7]);                \
} while (0)

__global__ void __launch_bounds__(NTHREADS, 3) vae_kernel(
    const float* __restrict__ adj,
    float* __restrict__ out_recon,
    float* __restrict__ out_mu,
    float* __restrict__ out_logvar)
{
    extern __shared__ unsigned char smem_raw[];
    Smem* s = (Smem*)smem_raw;
    const int tid = threadIdx.x;

    // ---- stage adj tile (vectorized, coalesced, read once from HBM) ----
    {
        const float4* src = (const float4*)(adj + (size_t)blockIdx.x * (BLOC * 676));
        float4* dst = (float4*)s->adj;
#pragma unroll 1
        for (int i = tid; i < (BLOC * 676) / 4; i += NTHREADS) dst[i] = src[i];
    }
    if (tid < 4 * NB) {
        s->si[tid] = ((const float*)gStage.si)[tid];
        s->ti[tid] = ((const float*)gStage.ti)[tid];
        s->so[tid] = ((const float*)gStage.so)[tid];
        s->to[tid] = ((const float*)gStage.to)[tid];
    }
    if (tid < 4) s->fe[tid] = gStage.fe[tid];
    __syncthreads();

    const int b_loc = tid / 13;
    const int n = tid - b_loc * 13;
    const size_t b = (size_t)blockIdx.x * BLOC + b_loc;

    const float* ab = s->adj + b_loc * 676 + n * 13;
    const float* xb = &s->x[b_loc][0][0];
    float* myx = &s->x[b_loc][n][0];

    // ---- init: x[n][:] = sum_m (sum_i adj[i][n][m]) * iw[m][:]  (packed) ----
    float xr[16];
    {
        u64 acc[8];
#pragma unroll
        for (int j = 0; j < 8; j++) acc[j] = 0ull;   // (0.0f,0.0f)
#pragma unroll
        for (int m = 0; m < 13; m++) {
            float a = (ab[m] + ab[169 + m]) + (ab[338 + m] + ab[507 + m]);
            u64 a2 = bcast2(a);
#pragma unroll
            for (int j = 0; j < 8; j++) acc[j] = fma2(a2, cP.iw2[m][j], acc[j]);
        }
#pragma unroll
        for (int j = 0; j < 8; j++) unpack2(acc[j], xr[2 * j], xr[2 * j + 1]);
    }
    STORE16(myx, xr);
    __syncthreads();

    // ---- 4 GIN layers ----
#pragma unroll 1
    for (int l = 0; l < 4; l++) {
        const int bnidx = l * 13 + n;
        const u64 si2 = bcast2(s->si[bnidx]);
        const u64 ti2 = bcast2(s->ti[bnidx]);
        const u64 so2 = bcast2(s->so[bnidx]);
        const u64 to2 = bcast2(s->to[bnidx]);
        const u64 fe2 = bcast2(s->fe[l]);

        // aggregation (packed): agg[j-pair] channel mapping j/2 -> adj channel
        u64 agg[8];
#pragma unroll
        for (int j = 0; j < 8; j++) agg[j] = mul2(fe2, pack2(xr[2 * j], xr[2 * j + 1]));
#pragma unroll
        for (int m = 0; m < 13; m++) {
            float a0 = ab[m], a1 = ab[169 + m], a2 = ab[338 + m], a3 = ab[507 + m];
            u64 xm[8];
            LOADP8(xm, xb + m * 16);
            u64 p0 = bcast2(a0), p1 = bcast2(a1), p2 = bcast2(a2), p3 = bcast2(a3);
            agg[0] = fma2(p0, xm[0], agg[0]);
            agg[1] = fma2(p0, xm[1], agg[1]);
            agg[2] = fma2(p1, xm[2], agg[2]);
            agg[3] = fma2(p1, xm[3], agg[3]);
            agg[4] = fma2(p2, xm[4], agg[4]);
            agg[5] = fma2(p2, xm[5], agg[5]);
            agg[6] = fma2(p3, xm[6], agg[6]);
            agg[7] = fma2(p3, xm[7], agg[7]);
        }
        float aggs[16];
#pragma unroll
        for (int j = 0; j < 8; j++) unpack2(agg[j], aggs[2 * j], aggs[2 * j + 1]);

        u64 h1p[8];
        mat16p(cP.w0p[l], cP.b02[l], aggs, h1p);
        float h1[16];
#pragma unroll
        for (int j = 0; j < 8; j++) {
            u64 t = fma2(si2, h1p[j], ti2);
            float lo, hi; unpack2(t, lo, hi);
            h1[2 * j] = leaky(lo); h1[2 * j + 1] = leaky(hi);
        }
        u64 h2p[8];
        mat16p(cP.w1p[l], cP.b12[l], h1, h2p);
#pragma unroll
        for (int j = 0; j < 8; j++) {
            u64 t = fma2(so2, h2p[j], to2);
            float lo, hi; unpack2(t, lo, hi);
            xr[2 * j] = leaky(lo); xr[2 * j + 1] = leaky(hi);
        }

        __syncthreads();
        STORE16(myx, xr);
        __syncthreads();
    }

    // ---- heads: mu / logvar ----
    float muS[16];
    {
        u64 mup[8], lvp[8];
        mat16p(cP.fc1p, cP.fc1b2, xr, mup);
        mat16p(cP.fc2p, cP.fc2b2, xr, lvp);
        float lvS[16];
#pragma unroll
        for (int j = 0; j < 8; j++) {
            unpack2(mup[j], muS[2 * j], muS[2 * j + 1]);
            unpack2(lvp[j], lvS[2 * j], lvS[2 * j + 1]);
        }
        const size_t mbase = (b * 13 + (size_t)n) * 16;
        STORE16(out_mu + mbase, muS);
        STORE16(out_logvar + mbase, lvS);
    }

    // ---- decoder: per k, temp = mu @ dec_w[k].T + dec_b[k]; recon = relu(temp temp^T) ----
#pragma unroll 1
    for (int k = 0; k < 4; k++) {
        u64 t2[8];
        mat16p(cP.dwp[k], cP.db2[k], muS, t2);
        __syncthreads();                 // previous k's reads of x done
        STOREP8(myx, t2);
        __syncthreads();
        float* ro = out_recon + (((b * 4 + (size_t)k) * 13) + (size_t)n) * 13;
#pragma unroll
        for (int m = 0; m < 13; m++) {
            u64 tm[8];
            LOADP8(tm, xb + m * 16);
            u64 acc2 = mul2(t2[0], tm[0]);
#pragma unroll
            for (int j = 1; j < 8; j++) acc2 = fma2(t2[j], tm[j], acc2);
            float lo, hi; unpack2(acc2, lo, hi);
            ro[m] = fmaxf(lo + hi, 0.f);
        }
    }
}

extern "C" void kernel_launch(void* const* d_in, const int* in_sizes, int n_in,
                              void* d_out, int out_size)
{
    const float* adj  = (const float*)d_in[0];
    const float* iw   = (const float*)d_in[1];
    const float* eps  = (const float*)d_in[2];
    const float* w0   = (const float*)d_in[3];
    const float* b0   = (const float*)d_in[4];
    const float* w1   = (const float*)d_in[5];
    const float* b1   = (const float*)d_in[6];
    const float* big  = (const float*)d_in[7];
    const float* bib  = (const float*)d_in[8];
    const float* bim  = (const float*)d_in[9];
    const float* biv  = (const float*)d_in[10];
    const float* bog  = (const float*)d_in[11];
    const float* bob  = (const float*)d_in[12];
    const float* bom  = (const float*)d_in[13];
    const float* bov  = (const float*)d_in[14];
    const float* f1w  = (const float*)d_in[15];
    const float* f1b  = (const float*)d_in[16];
    const float* f2w  = (const float*)d_in[17];
    const float* f2b  = (const float*)d_in[18];
    const float* dw   = (const float*)d_in[19];
    const float* db   = (const float*)d_in[20];

    float* out = (float*)d_out;
    float* recon = out;                                   // 32768*4*13*13
    float* mu    = out + (size_t)BTOT * 676;              // 32768*13*16
    float* lv    = mu  + (size_t)BTOT * 208;

    pack_kernel<<<1, 256>>>(iw, eps, w0, b0, w1, b1,
                            big, bib, bim, biv, bog, bob, bom, bov,
                            f1w, f1b, f2w, f2b, dw, db);

    void* stage_ptr = nullptr;
    cudaGetSymbolAddress(&stage_ptr, gStage);
    cudaMemcpyToSymbolAsync(cP, stage_ptr, sizeof(CParams), 0,
                            cudaMemcpyDeviceToDevice, 0);

    const int shmem = (int)sizeof(Smem);
    cudaFuncSetAttribute(vae_kernel, cudaFuncAttributeMaxDynamicSharedMemorySize, shmem);
    vae_kernel<<<BTOT / BLOC, NTHREADS, shmem>>>(adj, recon, mu, lv);
}

// round 6
// speedup vs baseline: 1.2444x; 1.2444x over previous
#include <cuda_runtime.h>
#include <cstddef>

#define BLOC 16
#define NTHREADS (BLOC * 13)   // 208
#define NB 13
#define DD 16
#define BTOT 32768

// ---------------- constant parameter block ----------------
struct CParams {
    float iw[NB][DD];          // init_weight [m][d]
    float w0[4][DD][DD];       // mlp_w0 [l][d][e]
    float w1[4][DD][DD];
    float dw[4][DD][DD];       // dec_w  [k][d][l]
    float fc1w[DD][DD];
    float fc2w[DD][DD];
    float b0[4][DD];
    float b1[4][DD];
    float db[4][DD];
    float fc1b[DD];
    float fc2b[DD];
    float si[4][NB];
    float ti[4][NB];
    float so[4][NB];
    float to[4][NB];
    float fe[4];
};

__constant__ CParams cP;
__device__ CParams gStage;

// ---------------- pack kernel ----------------
__global__ void pack_kernel(
    const float* __restrict__ init_weight,
    const float* __restrict__ eps_param,
    const float* __restrict__ mlp_w0, const float* __restrict__ mlp_b0,
    const float* __restrict__ mlp_w1, const float* __restrict__ mlp_b1,
    const float* __restrict__ big, const float* __restrict__ bib,
    const float* __restrict__ bim, const float* __restrict__ biv,
    const float* __restrict__ bog, const float* __restrict__ bob,
    const float* __restrict__ bom, const float* __restrict__ bov,
    const float* __restrict__ fc1w, const float* __restrict__ fc1b,
    const float* __restrict__ fc2w, const float* __restrict__ fc2b,
    const float* __restrict__ decw, const float* __restrict__ decb)
{
    const int t = threadIdx.x;
    CParams* s = &gStage;
    for (int i = t; i < NB * DD; i += 256) ((float*)s->iw)[i] = init_weight[i];
    for (int i = t; i < 4 * DD * DD; i += 256) {
        ((float*)s->w0)[i] = mlp_w0[i];
        ((float*)s->w1)[i] = mlp_w1[i];
        ((float*)s->dw)[i] = decw[i];
    }
    for (int i = t; i < DD * DD; i += 256) {
        ((float*)s->fc1w)[i] = fc1w[i];
        ((float*)s->fc2w)[i] = fc2w[i];
    }
    if (t < 4 * DD) {
        ((float*)s->b0)[t] = mlp_b0[t];
        ((float*)s->b1)[t] = mlp_b1[t];
        ((float*)s->db)[t] = decb[t];
    }
    if (t < DD) {
        ((float*)s->fc1b)[t] = fc1b[t];
        ((float*)s->fc2b)[t] = fc2b[t];
    }
    if (t < 4 * NB) {
        float siv = big[t] * rsqrtf(biv[t] + 1e-5f);
        float sov = bog[t] * rsqrtf(bov[t] + 1e-5f);
        ((float*)s->si)[t] = siv;
        ((float*)s->ti)[t] = bib[t] - bim[t] * siv;
        ((float*)s->so)[t] = sov;
        ((float*)s->to)[t] = bob[t] - bom[t] * sov;
    }
    if (t < 4) s->fe[t] = 1.f + eps_param[t];
}

// ---------------- main kernel ----------------
struct Smem {
    float4 adj[BLOC * 169];       // [b_loc][(n*13+m)] -> 4 channels packed
    float x[2][BLOC][NB][DD];     // ping-pong node features
    float si[4 * NB], ti[4 * NB], so[4 * NB], to[4 * NB];
    float fe[4];
};                                 // ~70.7 KB -> 3 blocks/SM

#define LOAD16(dst, src) do {                                   \
    const float4* _p = (const float4*)(src);                    \
    float4 _a = _p[0], _b = _p[1], _c = _p[2], _d = _p[3];      \
    (dst)[0]=_a.x; (dst)[1]=_a.y; (dst)[2]=_a.z; (dst)[3]=_a.w; \
    (dst)[4]=_b.x; (dst)[5]=_b.y; (dst)[6]=_b.z; (dst)[7]=_b.w; \
    (dst)[8]=_c.x; (dst)[9]=_c.y; (dst)[10]=_c.z; (dst)[11]=_c.w;\
    (dst)[12]=_d.x;(dst)[13]=_d.y;(dst)[14]=_d.z;(dst)[15]=_d.w;\
} while (0)

#define STORE16(dst, src) do {                                  \
    float4* _p = (float4*)(dst);                                \
    _p[0] = make_float4((src)[0],(src)[1],(src)[2],(src)[3]);   \
    _p[1] = make_float4((src)[4],(src)[5],(src)[6],(src)[7]);   \
    _p[2] = make_float4((src)[8],(src)[9],(src)[10],(src)[11]); \
    _p[3] = make_float4((src)[12],(src)[13],(src)[14],(src)[15]);\
} while (0)

__device__ __forceinline__ float leaky(float v) {
    return v >= 0.f ? v : 0.01f * v;
}

__device__ __forceinline__ void mat16c(const float (*__restrict__ w)[DD],
                                       const float* __restrict__ bias,
                                       const float* __restrict__ v,
                                       float* __restrict__ out)
{
#pragma unroll
    for (int d = 0; d < 16; d++) {
        float acc = bias[d];
#pragma unroll
        for (int e = 0; e < 16; e++) acc = fmaf(v[e], w[d][e], acc);
        out[d] = acc;
    }
}

__global__ void __launch_bounds__(NTHREADS, 3) vae_kernel(
    const float* __restrict__ adj,
    float* __restrict__ out_recon,
    float* __restrict__ out_mu,
    float* __restrict__ out_logvar)
{
    extern __shared__ unsigned char smem_raw[];
    Smem* s = (Smem*)smem_raw;
    const int tid = threadIdx.x;

    // ---- stage adj with channel transpose: [i][n][m] -> [(n,m)][i] quad ----
    {
        const float* src = adj + (size_t)blockIdx.x * (BLOC * 676);
#pragma unroll 1
        for (int idx = tid; idx < BLOC * 169; idx += NTHREADS) {
            int bl = idx / 169;
            int nm = idx - bl * 169;
            const float* p = src + bl * 676 + nm;          // channel 0
            float4 q;
            q.x = p[0];
            q.y = p[169];
            q.z = p[338];
            q.w = p[507];
            s->adj[idx] = q;                                // conflict-free STS.128
        }
    }
    if (tid < 4 * NB) {
        s->si[tid] = ((const float*)gStage.si)[tid];
        s->ti[tid] = ((const float*)gStage.ti)[tid];
        s->so[tid] = ((const float*)gStage.so)[tid];
        s->to[tid] = ((const float*)gStage.to)[tid];
    }
    if (tid < 4) s->fe[tid] = gStage.fe[tid];
    __syncthreads();

    const int b_loc = tid / 13;
    const int n = tid - b_loc * 13;
    const size_t b = (size_t)blockIdx.x * BLOC + b_loc;

    const float4* ab4 = s->adj + b_loc * 169 + n * 13;

    // ---- init: x[n][d] = sum_m (sum_i adj[i][n][m]) * iw[m][d] ----
    float xr[16];
#pragma unroll
    for (int d = 0; d < 16; d++) xr[d] = 0.f;
#pragma unroll
    for (int m = 0; m < 13; m++) {
        float4 a = ab4[m];
        float asum = (a.x + a.y) + (a.z + a.w);
#pragma unroll
        for (int d = 0; d < 16; d++) xr[d] = fmaf(asum, cP.iw[m][d], xr[d]);
    }
    STORE16(&s->x[0][b_loc][n][0], xr);
    __syncthreads();

    // ---- 4 GIN layers (ping-pong x, ONE barrier per layer) ----
#pragma unroll 1
    for (int l = 0; l < 4; l++) {
        const int bnidx = l * 13 + n;
        const float si = s->si[bnidx];
        const float ti = s->ti[bnidx];
        const float so = s->so[bnidx];
        const float to = s->to[bnidx];
        const float fe = s->fe[l];

        const float* xbR = &s->x[l & 1][b_loc][0][0];

        float agg[16];
#pragma unroll
        for (int d = 0; d < 16; d++) agg[d] = fe * xr[d];
#pragma unroll
        for (int m = 0; m < 13; m++) {
            float4 a = ab4[m];
            float xm[16];
            LOAD16(xm, xbR + m * 16);
#pragma unroll
            for (int g = 0; g < 4; g++) {
                agg[g]      = fmaf(a.x, xm[g],      agg[g]);
                agg[4 + g]  = fmaf(a.y, xm[4 + g],  agg[4 + g]);
                agg[8 + g]  = fmaf(a.z, xm[8 + g],  agg[8 + g]);
                agg[12 + g] = fmaf(a.w, xm[12 + g], agg[12 + g]);
            }
        }
        float h1[16];
        mat16c(cP.w0[l], cP.b0[l], agg, h1);
#pragma unroll
        for (int d = 0; d < 16; d++) h1[d] = leaky(fmaf(si, h1[d], ti));
        float h2[16];
        mat16c(cP.w1[l], cP.b1[l], h1, h2);
#pragma unroll
        for (int d = 0; d < 16; d++) xr[d] = leaky(fmaf(so, h2[d], to));

        // write to the OTHER buffer; single barrier
        STORE16(&s->x[(l + 1) & 1][b_loc][n][0], xr);
        __syncthreads();
    }

    // ---- heads: mu / logvar (from registers) ----
    float mu[16], lv[16];
    mat16c(cP.fc1w, cP.fc1b, xr, mu);
    mat16c(cP.fc2w, cP.fc2b, xr, lv);
    {
        const size_t mbase = (b * 13 + (size_t)n) * 16;
        STORE16(out_mu + mbase, mu);
        STORE16(out_logvar + mbase, lv);
    }

    // ---- decoder: ping-pong temp buffers, ONE barrier per k ----
#pragma unroll 1
    for (int k = 0; k < 4; k++) {
        float t[16];
        mat16c(cP.dw[k], cP.db[k], mu, t);
        STORE16(&s->x[k & 1][b_loc][n][0], t);
        __syncthreads();
        const float* tb = &s->x[k & 1][b_loc][0][0];
        float* ro = out_recon + (((b * 4 + (size_t)k) * 13) + (size_t)n) * 13;
#pragma unroll
        for (int m = 0; m < 13; m++) {
            float tm[16];
            LOAD16(tm, tb + m * 16);
            float acc = t[0] * tm[0];
#pragma unroll
            for (int j = 1; j < 16; j++) acc = fmaf(t[j], tm[j], acc);
            ro[m] = fmaxf(acc, 0.f);
        }
    }
}

extern "C" void kernel_launch(void* const* d_in, const int* in_sizes, int n_in,
                              void* d_out, int out_size)
{
    const float* adj  = (const float*)d_in[0];
    const float* iw   = (const float*)d_in[1];
    const float* eps  = (const float*)d_in[2];
    const float* w0   = (const float*)d_in[3];
    const float* b0   = (const float*)d_in[4];
    const float* w1   = (const float*)d_in[5];
    const float* b1   = (const float*)d_in[6];
    const float* big  = (const float*)d_in[7];
    const float* bib  = (const float*)d_in[8];
    const float* bim  = (const float*)d_in[9];
    const float* biv  = (const float*)d_in[10];
    const float* bog  = (const float*)d_in[11];
    const float* bob  = (const float*)d_in[12];
    const float* bom  = (const float*)d_in[13];
    const float* bov  = (const float*)d_in[14];
    const float* f1w  = (const float*)d_in[15];
    const float* f1b  = (const float*)d_in[16];
    const float* f2w  = (const float*)d_in[17];
    const float* f2b  = (const float*)d_in[18];
    const float* dw   = (const float*)d_in[19];
    const float* db   = (const float*)d_in[20];

    float* out = (float*)d_out;
    float* recon = out;                                   // 32768*4*13*13
    float* mu    = out + (size_t)BTOT * 676;              // 32768*13*16
    float* lv    = mu  + (size_t)BTOT * 208;

    pack_kernel<<<1, 256>>>(iw, eps, w0, b0, w1, b1,
                            big, bib, bim, biv, bog, bob, bom, bov,
                            f1w, f1b, f2w, f2b, dw, db);

    void* stage_ptr = nullptr;
    cudaGetSymbolAddress(&stage_ptr, gStage);
    cudaMemcpyToSymbolAsync(cP, stage_ptr, sizeof(CParams), 0,
                            cudaMemcpyDeviceToDevice, 0);

    const int shmem = (int)sizeof(Smem);
    cudaFuncSetAttribute(vae_kernel, cudaFuncAttributeMaxDynamicSharedMemorySize, shmem);
    vae_kernel<<<BTOT / BLOC, NTHREADS, shmem>>>(adj, recon, mu, lv);
}

// round 7
// speedup vs baseline: 1.5564x; 1.2508x over previous
#include <cuda_runtime.h>
#include <cstddef>

#define BLOC 16
#define NTHREADS (BLOC * 13)   // 208
#define NB 13
#define DD 16
#define BTOT 32768

// ---------------- constant parameter block ----------------
struct CParams {
    float iw[NB][DD];          // init_weight [m][d]
    float w0[4][DD][DD];       // mlp_w0 [l][d][e]
    float w1[4][DD][DD];
    float dw[4][DD][DD];       // dec_w  [k][d][l]
    float fc1w[DD][DD];
    float fc2w[DD][DD];
    float b0[4][DD];
    float b1[4][DD];
    float db[4][DD];
    float fc1b[DD];
    float fc2b[DD];
    float si[4][NB];
    float ti[4][NB];
    float so[4][NB];
    float to[4][NB];
    float fe[4];
};

__constant__ CParams cP;
__device__ CParams gStage;

// ---------------- pack kernel ----------------
__global__ void pack_kernel(
    const float* __restrict__ init_weight,
    const float* __restrict__ eps_param,
    const float* __restrict__ mlp_w0, const float* __restrict__ mlp_b0,
    const float* __restrict__ mlp_w1, const float* __restrict__ mlp_b1,
    const float* __restrict__ big, const float* __restrict__ bib,
    const float* __restrict__ bim, const float* __restrict__ biv,
    const float* __restrict__ bog, const float* __restrict__ bob,
    const float* __restrict__ bom, const float* __restrict__ bov,
    const float* __restrict__ fc1w, const float* __restrict__ fc1b,
    const float* __restrict__ fc2w, const float* __restrict__ fc2b,
    const float* __restrict__ decw, const float* __restrict__ decb)
{
    const int t = threadIdx.x;
    CParams* s = &gStage;
    for (int i = t; i < NB * DD; i += 256) ((float*)s->iw)[i] = init_weight[i];
    for (int i = t; i < 4 * DD * DD; i += 256) {
        ((float*)s->w0)[i] = mlp_w0[i];
        ((float*)s->w1)[i] = mlp_w1[i];
        ((float*)s->dw)[i] = decw[i];
    }
    for (int i = t; i < DD * DD; i += 256) {
        ((float*)s->fc1w)[i] = fc1w[i];
        ((float*)s->fc2w)[i] = fc2w[i];
    }
    if (t < 4 * DD) {
        ((float*)s->b0)[t] = mlp_b0[t];
        ((float*)s->b1)[t] = mlp_b1[t];
        ((float*)s->db)[t] = decb[t];
    }
    if (t < DD) {
        ((float*)s->fc1b)[t] = fc1b[t];
        ((float*)s->fc2b)[t] = fc2b[t];
    }
    if (t < 4 * NB) {
        float siv = big[t] * rsqrtf(biv[t] + 1e-5f);
        float sov = bog[t] * rsqrtf(bov[t] + 1e-5f);
        ((float*)s->si)[t] = siv;
        ((float*)s->ti)[t] = bib[t] - bim[t] * siv;
        ((float*)s->so)[t] = sov;
        ((float*)s->to)[t] = bob[t] - bom[t] * sov;
    }
    if (t < 4) s->fe[t] = 1.f + eps_param[t];
}

// ---------------- main kernel ----------------
struct Smem {
    float4 adj[BLOC * 169];       // [b_loc][(n*13+m)] -> 4 channels packed
    float x[2][BLOC][NB][DD];     // ping-pong node features
    float si[4 * NB], ti[4 * NB], so[4 * NB], to[4 * NB];
    float fe[4];
};                                 // ~70.7 KB -> 3 blocks/SM

#define LOAD16(dst, src) do {                                   \
    const float4* _p = (const float4*)(src);                    \
    float4 _a = _p[0], _b = _p[1], _c = _p[2], _d = _p[3];      \
    (dst)[0]=_a.x; (dst)[1]=_a.y; (dst)[2]=_a.z; (dst)[3]=_a.w; \
    (dst)[4]=_b.x; (dst)[5]=_b.y; (dst)[6]=_b.z; (dst)[7]=_b.w; \
    (dst)[8]=_c.x; (dst)[9]=_c.y; (dst)[10]=_c.z; (dst)[11]=_c.w;\
    (dst)[12]=_d.x;(dst)[13]=_d.y;(dst)[14]=_d.z;(dst)[15]=_d.w;\
} while (0)

#define STORE16(dst, src) do {                                  \
    float4* _p = (float4*)(dst);                                \
    _p[0] = make_float4((src)[0],(src)[1],(src)[2],(src)[3]);   \
    _p[1] = make_float4((src)[4],(src)[5],(src)[6],(src)[7]);   \
    _p[2] = make_float4((src)[8],(src)[9],(src)[10],(src)[11]); \
    _p[3] = make_float4((src)[12],(src)[13],(src)[14],(src)[15]);\
} while (0)

__device__ __forceinline__ float leaky(float v) {
    return v >= 0.f ? v : 0.01f * v;
}

// out[d] = bias[d] + sum_e v[e] * w[d][e]
// weights / bias fetched as explicit float4 -> LDC.128 (Blackwell has no
// cbank-as-ALU-operand; scalar LDC would double the issue count)
__device__ __forceinline__ void mat16c(const float (*__restrict__ w)[DD],
                                       const float* __restrict__ bias,
                                       const float* __restrict__ v,
                                       float* __restrict__ out)
{
    const float4* bq = (const float4*)bias;
    float4 b0 = bq[0], b1 = bq[1], b2 = bq[2], b3 = bq[3];
    float bs[16] = { b0.x,b0.y,b0.z,b0.w, b1.x,b1.y,b1.z,b1.w,
                     b2.x,b2.y,b2.z,b2.w, b3.x,b3.y,b3.z,b3.w };
#pragma unroll
    for (int d = 0; d < 16; d++) {
        const float4* row = (const float4*)w[d];
        float4 r0 = row[0], r1 = row[1], r2 = row[2], r3 = row[3];
        float acc = bs[d];
        acc = fmaf(v[0],  r0.x, acc); acc = fmaf(v[1],  r0.y, acc);
        acc = fmaf(v[2],  r0.z, acc); acc = fmaf(v[3],  r0.w, acc);
        acc = fmaf(v[4],  r1.x, acc); acc = fmaf(v[5],  r1.y, acc);
        acc = fmaf(v[6],  r1.z, acc); acc = fmaf(v[7],  r1.w, acc);
        acc = fmaf(v[8],  r2.x, acc); acc = fmaf(v[9],  r2.y, acc);
        acc = fmaf(v[10], r2.z, acc); acc = fmaf(v[11], r2.w, acc);
        acc = fmaf(v[12], r3.x, acc); acc = fmaf(v[13], r3.y, acc);
        acc = fmaf(v[14], r3.z, acc); acc = fmaf(v[15], r3.w, acc);
        out[d] = acc;
    }
}

__global__ void __launch_bounds__(NTHREADS, 3) vae_kernel(
    const float* __restrict__ adj,
    float* __restrict__ out_recon,
    float* __restrict__ out_mu,
    float* __restrict__ out_logvar)
{
    extern __shared__ unsigned char smem_raw[];
    Smem* s = (Smem*)smem_raw;
    const int tid = threadIdx.x;

    // ---- stage adj with channel transpose: [i][n][m] -> [(n,m)][i] quad ----
    {
        const float* src = adj + (size_t)blockIdx.x * (BLOC * 676);
#pragma unroll 1
        for (int idx = tid; idx < BLOC * 169; idx += NTHREADS) {
            int bl = idx / 169;
            int nm = idx - bl * 169;
            const float* p = src + bl * 676 + nm;
            float4 q;
            q.x = p[0];
            q.y = p[169];
            q.z = p[338];
            q.w = p[507];
            s->adj[idx] = q;
        }
    }
    if (tid < 4 * NB) {
        s->si[tid] = ((const float*)gStage.si)[tid];
        s->ti[tid] = ((const float*)gStage.ti)[tid];
        s->so[tid] = ((const float*)gStage.so)[tid];
        s->to[tid] = ((const float*)gStage.to)[tid];
    }
    if (tid < 4) s->fe[tid] = gStage.fe[tid];
    __syncthreads();

    const int b_loc = tid / 13;
    const int n = tid - b_loc * 13;
    const size_t b = (size_t)blockIdx.x * BLOC + b_loc;

    const float4* ab4 = s->adj + b_loc * 169 + n * 13;

    // ---- init: x[n][d] = sum_m (sum_i adj[i][n][m]) * iw[m][d] ----
    float xr[16];
#pragma unroll
    for (int d = 0; d < 16; d++) xr[d] = 0.f;
#pragma unroll
    for (int m = 0; m < 13; m++) {
        float4 a = ab4[m];
        float asum = (a.x + a.y) + (a.z + a.w);
        const float4* wq = (const float4*)cP.iw[m];
        float4 w0q = wq[0], w1q = wq[1], w2q = wq[2], w3q = wq[3];
        xr[0]  = fmaf(asum, w0q.x, xr[0]);  xr[1]  = fmaf(asum, w0q.y, xr[1]);
        xr[2]  = fmaf(asum, w0q.z, xr[2]);  xr[3]  = fmaf(asum, w0q.w, xr[3]);
        xr[4]  = fmaf(asum, w1q.x, xr[4]);  xr[5]  = fmaf(asum, w1q.y, xr[5]);
        xr[6]  = fmaf(asum, w1q.z, xr[6]);  xr[7]  = fmaf(asum, w1q.w, xr[7]);
        xr[8]  = fmaf(asum, w2q.x, xr[8]);  xr[9]  = fmaf(asum, w2q.y, xr[9]);
        xr[10] = fmaf(asum, w2q.z, xr[10]); xr[11] = fmaf(asum, w2q.w, xr[11]);
        xr[12] = fmaf(asum, w3q.x, xr[12]); xr[13] = fmaf(asum, w3q.y, xr[13]);
        xr[14] = fmaf(asum, w3q.z, xr[14]); xr[15] = fmaf(asum, w3q.w, xr[15]);
    }
    STORE16(&s->x[0][b_loc][n][0], xr);
    __syncthreads();

    // ---- 4 GIN layers (ping-pong x, ONE barrier per layer) ----
#pragma unroll 1
    for (int l = 0; l < 4; l++) {
        const int bnidx = l * 13 + n;
        const float si = s->si[bnidx];
        const float ti = s->ti[bnidx];
        const float so = s->so[bnidx];
        const float to = s->to[bnidx];
        const float fe = s->fe[l];

        const float* xbR = &s->x[l & 1][b_loc][0][0];

        float agg[16];
#pragma unroll
        for (int d = 0; d < 16; d++) agg[d] = fe * xr[d];
#pragma unroll
        for (int m = 0; m < 13; m++) {
            float4 a = ab4[m];
            float xm[16];
            LOAD16(xm, xbR + m * 16);
#pragma unroll
            for (int g = 0; g < 4; g++) {
                agg[g]      = fmaf(a.x, xm[g],      agg[g]);
                agg[4 + g]  = fmaf(a.y, xm[4 + g],  agg[4 + g]);
                agg[8 + g]  = fmaf(a.z, xm[8 + g],  agg[8 + g]);
                agg[12 + g] = fmaf(a.w, xm[12 + g], agg[12 + g]);
            }
        }
        float h1[16];
        mat16c(cP.w0[l], cP.b0[l], agg, h1);
#pragma unroll
        for (int d = 0; d < 16; d++) h1[d] = leaky(fmaf(si, h1[d], ti));
        float h2[16];
        mat16c(cP.w1[l], cP.b1[l], h1, h2);
#pragma unroll
        for (int d = 0; d < 16; d++) xr[d] = leaky(fmaf(so, h2[d], to));

        STORE16(&s->x[(l + 1) & 1][b_loc][n][0], xr);
        __syncthreads();
    }

    // ---- heads: mu / logvar ----
    float mu[16], lv[16];
    mat16c(cP.fc1w, cP.fc1b, xr, mu);
    mat16c(cP.fc2w, cP.fc2b, xr, lv);
    {
        const size_t mbase = (b * 13 + (size_t)n) * 16;
        STORE16(out_mu + mbase, mu);
        STORE16(out_logvar + mbase, lv);
    }

    // ---- decoder: ping-pong temp buffers, ONE barrier per k ----
#pragma unroll 1
    for (int k = 0; k < 4; k++) {
        float t[16];
        mat16c(cP.dw[k], cP.db[k], mu, t);
        STORE16(&s->x[k & 1][b_loc][n][0], t);
        __syncthreads();
        const float* tb = &s->x[k & 1][b_loc][0][0];
        float* ro = out_recon + (((b * 4 + (size_t)k) * 13) + (size_t)n) * 13;
#pragma unroll
        for (int m = 0; m < 13; m++) {
            float tm[16];
            LOAD16(tm, tb + m * 16);
            float acc = t[0] * tm[0];
#pragma unroll
            for (int j = 1; j < 16; j++) acc = fmaf(t[j], tm[j], acc);
            ro[m] = fmaxf(acc, 0.f);
        }
    }
}

extern "C" void kernel_launch(void* const* d_in, const int* in_sizes, int n_in,
                              void* d_out, int out_size)
{
    const float* adj  = (const float*)d_in[0];
    const float* iw   = (const float*)d_in[1];
    const float* eps  = (const float*)d_in[2];
    const float* w0   = (const float*)d_in[3];
    const float* b0   = (const float*)d_in[4];
    const float* w1   = (const float*)d_in[5];
    const float* b1   = (const float*)d_in[6];
    const float* big  = (const float*)d_in[7];
    const float* bib  = (const float*)d_in[8];
    const float* bim  = (const float*)d_in[9];
    const float* biv  = (const float*)d_in[10];
    const float* bog  = (const float*)d_in[11];
    const float* bob  = (const float*)d_in[12];
    const float* bom  = (const float*)d_in[13];
    const float* bov  = (const float*)d_in[14];
    const float* f1w  = (const float*)d_in[15];
    const float* f1b  = (const float*)d_in[16];
    const float* f2w  = (const float*)d_in[17];
    const float* f2b  = (const float*)d_in[18];
    const float* dw   = (const float*)d_in[19];
    const float* db   = (const float*)d_in[20];

    float* out = (float*)d_out;
    float* recon = out;                                   // 32768*4*13*13
    float* mu    = out + (size_t)BTOT * 676;              // 32768*13*16
    float* lv    = mu  + (size_t)BTOT * 208;

    pack_kernel<<<1, 256>>>(iw, eps, w0, b0, w1, b1,
                            big, bib, bim, biv, bog, bob, bom, bov,
                            f1w, f1b, f2w, f2b, dw, db);

    void* stage_ptr = nullptr;
    cudaGetSymbolAddress(&stage_ptr, gStage);
    cudaMemcpyToSymbolAsync(cP, stage_ptr, sizeof(CParams), 0,
                            cudaMemcpyDeviceToDevice, 0);

    const int shmem = (int)sizeof(Smem);
    cudaFuncSetAttribute(vae_kernel, cudaFuncAttributeMaxDynamicSharedMemorySize, shmem);
    vae_kernel<<<BTOT / BLOC, NTHREADS, shmem>>>(adj, recon, mu, lv);
}

// round 8
// speedup vs baseline: 1.6890x; 1.0852x over previous
#include <cuda_runtime.h>
#include <cstddef>

#define BLOC 16
#define NTHREADS (BLOC * 13)   // 208
#define NB 13
#define DD 16
#define BTOT 32768

typedef unsigned long long u64;

// ---------------- packed constant parameter block ----------------
// All weight tables stored transposed [e][d] with d contiguous, as ulonglong2
// quads: one LDC.128 yields two f32x2 operand pairs directly in register pairs.
struct CParams {
    ulonglong2 iwq[NB][4];        // iw[m][4q..4q+3]  (d contiguous already)
    ulonglong2 w0q[4][DD][4];     // [l][e][q] = {w0[l][4q][e], w0[l][4q+1][e], w0[l][4q+2][e], w0[l][4q+3][e]}
    ulonglong2 w1q[4][DD][4];
    ulonglong2 dwq[4][DD][4];
    ulonglong2 fc1q[DD][4];
    ulonglong2 fc2q[DD][4];
    ulonglong2 b0q[4][4];         // bias quads [l][q] = {b[4q..4q+3]}
    ulonglong2 b1q[4][4];
    ulonglong2 dbq[4][4];
    ulonglong2 fc1bq[4];
    ulonglong2 fc2bq[4];
    float si[4][NB];
    float ti[4][NB];
    float so[4][NB];
    float to[4][NB];
    float fe[4];
};

__constant__ CParams cP;
__device__ CParams gStage;

// ---------------- pack kernel ----------------
__global__ void pack_kernel(
    const float* __restrict__ init_weight,
    const float* __restrict__ eps_param,
    const float* __restrict__ mlp_w0, const float* __restrict__ mlp_b0,
    const float* __restrict__ mlp_w1, const float* __restrict__ mlp_b1,
    const float* __restrict__ big, const float* __restrict__ bib,
    const float* __restrict__ bim, const float* __restrict__ biv,
    const float* __restrict__ bog, const float* __restrict__ bob,
    const float* __restrict__ bom, const float* __restrict__ bov,
    const float* __restrict__ fc1w, const float* __restrict__ fc1b,
    const float* __restrict__ fc2w, const float* __restrict__ fc2b,
    const float* __restrict__ decw, const float* __restrict__ decb)
{
    const int t = threadIdx.x;
    CParams* s = &gStage;

    // iwq: d contiguous, straight copy
    for (int i = t; i < NB * DD; i += 256)
        ((float*)s->iwq)[i] = init_weight[i];

    // transposed MLP / decoder weights: dst[l][e][d] = src[l][d][e]
    for (int i = t; i < 4 * DD * DD; i += 256) {
        int d = i % DD;
        int e = (i / DD) % DD;
        int l = i / (DD * DD);
        ((float*)s->w0q)[i] = mlp_w0[l * 256 + d * DD + e];
        ((float*)s->w1q)[i] = mlp_w1[l * 256 + d * DD + e];
        ((float*)s->dwq)[i] = decw[l * 256 + d * DD + e];
    }
    for (int i = t; i < DD * DD; i += 256) {
        int d = i % DD;
        int e = i / DD;
        ((float*)s->fc1q)[i] = fc1w[d * DD + e];
        ((float*)s->fc2q)[i] = fc2w[d * DD + e];
    }
    if (t < 4 * DD) {
        ((float*)s->b0q)[t] = mlp_b0[t];
        ((float*)s->b1q)[t] = mlp_b1[t];
        ((float*)s->dbq)[t] = decb[t];
    }
    if (t < DD) {
        ((float*)s->fc1bq)[t] = fc1b[t];
        ((float*)s->fc2bq)[t] = fc2b[t];
    }
    if (t < 4 * NB) {
        float siv = big[t] * rsqrtf(biv[t] + 1e-5f);
        float sov = bog[t] * rsqrtf(bov[t] + 1e-5f);
        ((float*)s->si)[t] = siv;
        ((float*)s->ti)[t] = bib[t] - bim[t] * siv;
        ((float*)s->so)[t] = sov;
        ((float*)s->to)[t] = bob[t] - bom[t] * sov;
    }
    if (t < 4) s->fe[t] = 1.f + eps_param[t];
}

// ---------------- f32x2 helpers ----------------
__device__ __forceinline__ u64 pack2(float lo, float hi) {
    u64 r; asm("mov.b64 %0, {%1, %2};" : "=l"(r) : "f"(lo), "f"(hi)); return r;
}
__device__ __forceinline__ u64 bcast2(float v) {
    u64 r; asm("mov.b64 %0, {%1, %1};" : "=l"(r) : "f"(v)); return r;
}
__device__ __forceinline__ void unpack2(u64 v, float& lo, float& hi) {
    asm("mov.b64 {%0, %1}, %2;" : "=f"(lo), "=f"(hi) : "l"(v));
}
__device__ __forceinline__ u64 fma2(u64 a, u64 b, u64 c) {
    u64 r; asm("fma.rn.f32x2 %0, %1, %2, %3;" : "=l"(r) : "l"(a), "l"(b), "l"(c)); return r;
}
__device__ __forceinline__ u64 mul2(u64 a, u64 b) {
    u64 r; asm("mul.rn.f32x2 %0, %1, %2;" : "=l"(r) : "l"(a), "l"(b)); return r;
}

__device__ __forceinline__ float leaky(float v) {
    return v >= 0.f ? v : 0.01f * v;
}

// out pairs (d-major): out[j] = pair(d=2j, d=2j+1); weights transposed [e][q].
// Each LDC.128 (ulonglong2) feeds 2 FFMA2 with zero repack movs.
__device__ __forceinline__ void mat16q(const ulonglong2 (*__restrict__ wq)[4],
                                       const ulonglong2* __restrict__ bq,
                                       const float* __restrict__ v,
                                       u64* __restrict__ out)
{
#pragma unroll
    for (int q = 0; q < 4; q++) {
        ulonglong2 bb = bq[q];
        out[2 * q] = bb.x;
        out[2 * q + 1] = bb.y;
    }
#pragma unroll
    for (int e = 0; e < DD; e++) {
        u64 ve = bcast2(v[e]);
#pragma unroll
        for (int q = 0; q < 4; q++) {
            ulonglong2 w = wq[e][q];
            out[2 * q]     = fma2(ve, w.x, out[2 * q]);
            out[2 * q + 1] = fma2(ve, w.y, out[2 * q + 1]);
        }
    }
}

// ---------------- main kernel ----------------
struct Smem {
    float4 adj[BLOC * 169];       // [b_loc][(n*13+m)] -> 4 channels packed
    float x[2][BLOC][NB][DD];     // ping-pong node features
    float si[4 * NB], ti[4 * NB], so[4 * NB], to[4 * NB];
    float fe[4];
};                                 // ~70.7 KB -> 3 blocks/SM

#define STORE16(dst, src) do {                                  \
    float4* _p = (float4*)(dst);                                \
    _p[0] = make_float4((src)[0],(src)[1],(src)[2],(src)[3]);   \
    _p[1] = make_float4((src)[4],(src)[5],(src)[6],(src)[7]);   \
    _p[2] = make_float4((src)[8],(src)[9],(src)[10],(src)[11]); \
    _p[3] = make_float4((src)[12],(src)[13],(src)[14],(src)[15]);\
} while (0)

#define STOREP8(dst, src) do {                                  \
    ulonglong2* _p = (ulonglong2*)(dst);                        \
    _p[0] = make_ulonglong2((src)[0], (src)[1]);                \
    _p[1] = make_ulonglong2((src)[2], (src)[3]);                \
    _p[2] = make_ulonglong2((src)[4], (src)[5]);                \
    _p[3] = make_ulonglong2((src)[6], (src)[7]);                \
} while (0)

__global__ void __launch_bounds__(NTHREADS, 3) vae_kernel(
    const float* __restrict__ adj,
    float* __restrict__ out_recon,
    float* __restrict__ out_mu,
    float* __restrict__ out_logvar)
{
    extern __shared__ unsigned char smem_raw[];
    Smem* s = (Smem*)smem_raw;
    const int tid = threadIdx.x;

    // ---- stage adj with channel transpose: [i][n][m] -> [(n,m)][i] quad ----
    {
        const float* src = adj + (size_t)blockIdx.x * (BLOC * 676);
#pragma unroll 1
        for (int idx = tid; idx < BLOC * 169; idx += NTHREADS) {
            int bl = idx / 169;
            int nm = idx - bl * 169;
            const float* p = src + bl * 676 + nm;
            float4 q;
            q.x = p[0];
            q.y = p[169];
            q.z = p[338];
            q.w = p[507];
            s->adj[idx] = q;
        }
    }
    if (tid < 4 * NB) {
        s->si[tid] = ((const float*)gStage.si)[tid];
        s->ti[tid] = ((const float*)gStage.ti)[tid];
        s->so[tid] = ((const float*)gStage.so)[tid];
        s->to[tid] = ((const float*)gStage.to)[tid];
    }
    if (tid < 4) s->fe[tid] = gStage.fe[tid];
    __syncthreads();

    const int b_loc = tid / 13;
    const int n = tid - b_loc * 13;
    const size_t b = (size_t)blockIdx.x * BLOC + b_loc;

    const float4* ab4 = s->adj + b_loc * 169 + n * 13;

    // ---- init: x[n][:] = sum_m (sum_i adj[i][n][m]) * iw[m][:]  (packed) ----
    float xr[16];
    {
        u64 acc[8];
#pragma unroll
        for (int j = 0; j < 8; j++) acc[j] = 0ull;
#pragma unroll
        for (int m = 0; m < 13; m++) {
            float4 a = ab4[m];
            u64 a2 = bcast2((a.x + a.y) + (a.z + a.w));
#pragma unroll
            for (int q = 0; q < 4; q++) {
                ulonglong2 w = cP.iwq[m][q];
                acc[2 * q]     = fma2(a2, w.x, acc[2 * q]);
                acc[2 * q + 1] = fma2(a2, w.y, acc[2 * q + 1]);
            }
        }
        STOREP8(&s->x[0][b_loc][n][0], acc);
#pragma unroll
        for (int j = 0; j < 8; j++) unpack2(acc[j], xr[2 * j], xr[2 * j + 1]);
    }
    __syncthreads();

    // ---- 4 GIN layers (ping-pong x, ONE barrier per layer) ----
#pragma unroll 1
    for (int l = 0; l < 4; l++) {
        const int bnidx = l * 13 + n;
        const u64 si2 = bcast2(s->si[bnidx]);
        const u64 ti2 = bcast2(s->ti[bnidx]);
        const u64 so2 = bcast2(s->so[bnidx]);
        const u64 to2 = bcast2(s->to[bnidx]);
        const u64 fe2 = bcast2(s->fe[l]);

        const float* xbR = &s->x[l & 1][b_loc][0][0];

        u64 agg[8];
#pragma unroll
        for (int j = 0; j < 8; j++) agg[j] = mul2(fe2, pack2(xr[2 * j], xr[2 * j + 1]));
#pragma unroll
        for (int m = 0; m < 13; m++) {
            float4 a = ab4[m];
            const ulonglong2* xq = (const ulonglong2*)(xbR + m * 16);
            ulonglong2 x0 = xq[0], x1 = xq[1], x2 = xq[2], x3 = xq[3];
            u64 p0 = bcast2(a.x), p1 = bcast2(a.y), p2 = bcast2(a.z), p3 = bcast2(a.w);
            agg[0] = fma2(p0, x0.x, agg[0]);
            agg[1] = fma2(p0, x0.y, agg[1]);
            agg[2] = fma2(p1, x1.x, agg[2]);
            agg[3] = fma2(p1, x1.y, agg[3]);
            agg[4] = fma2(p2, x2.x, agg[4]);
            agg[5] = fma2(p2, x2.y, agg[5]);
            agg[6] = fma2(p3, x3.x, agg[6]);
            agg[7] = fma2(p3, x3.y, agg[7]);
        }
        float aggs[16];
#pragma unroll
        for (int j = 0; j < 8; j++) unpack2(agg[j], aggs[2 * j], aggs[2 * j + 1]);

        u64 h1p[8];
        mat16q(cP.w0q[l], cP.b0q[l], aggs, h1p);
        float h1[16];
#pragma unroll
        for (int j = 0; j < 8; j++) {
            u64 t = fma2(si2, h1p[j], ti2);
            float lo, hi; unpack2(t, lo, hi);
            h1[2 * j] = leaky(lo); h1[2 * j + 1] = leaky(hi);
        }
        u64 h2p[8];
        mat16q(cP.w1q[l], cP.b1q[l], h1, h2p);
#pragma unroll
        for (int j = 0; j < 8; j++) {
            u64 t = fma2(so2, h2p[j], to2);
            float lo, hi; unpack2(t, lo, hi);
            xr[2 * j] = leaky(lo); xr[2 * j + 1] = leaky(hi);
        }

        STORE16(&s->x[(l + 1) & 1][b_loc][n][0], xr);
        __syncthreads();
    }

    // ---- heads: mu / logvar ----
    float muS[16];
    {
        u64 mup[8], lvp[8];
        mat16q(cP.fc1q, cP.fc1bq, xr, mup);
        mat16q(cP.fc2q, cP.fc2bq, xr, lvp);
        const size_t mbase = (b * 13 + (size_t)n) * 16;
        STOREP8(out_mu + mbase, mup);
        STOREP8(out_logvar + mbase, lvp);
#pragma unroll
        for (int j = 0; j < 8; j++) unpack2(mup[j], muS[2 * j], muS[2 * j + 1]);
    }

    // ---- decoder: ping-pong temp buffers, ONE barrier per k ----
#pragma unroll 1
    for (int k = 0; k < 4; k++) {
        u64 t2[8];
        mat16q(cP.dwq[k], cP.dbq[k], muS, t2);
        STOREP8(&s->x[k & 1][b_loc][n][0], t2);
        __syncthreads();
        const float* tb = &s->x[k & 1][b_loc][0][0];
        float* ro = out_recon + (((b * 4 + (size_t)k) * 13) + (size_t)n) * 13;
#pragma unroll
        for (int m = 0; m < 13; m++) {
            const ulonglong2* tq = (const ulonglong2*)(tb + m * 16);
            ulonglong2 q0 = tq[0], q1 = tq[1], q2 = tq[2], q3 = tq[3];
            u64 acc2 = mul2(t2[0], q0.x);
            acc2 = fma2(t2[1], q0.y, acc2);
            acc2 = fma2(t2[2], q1.x, acc2);
            acc2 = fma2(t2[3], q1.y, acc2);
            acc2 = fma2(t2[4], q2.x, acc2);
            acc2 = fma2(t2[5], q2.y, acc2);
            acc2 = fma2(t2[6], q3.x, acc2);
            acc2 = fma2(t2[7], q3.y, acc2);
            float lo, hi; unpack2(acc2, lo, hi);
            ro[m] = fmaxf(lo + hi, 0.f);
        }
    }
}

extern "C" void kernel_launch(void* const* d_in, const int* in_sizes, int n_in,
                              void* d_out, int out_size)
{
    const float* adj  = (const float*)d_in[0];
    const float* iw   = (const float*)d_in[1];
    const float* eps  = (const float*)d_in[2];
    const float* w0   = (const float*)d_in[3];
    const float* b0   = (const float*)d_in[4];
    const float* w1   = (const float*)d_in[5];
    const float* b1   = (const float*)d_in[6];
    const float* big  = (const float*)d_in[7];
    const float* bib  = (const float*)d_in[8];
    const float* bim  = (const float*)d_in[9];
    const float* biv  = (const float*)d_in[10];
    const float* bog  = (const float*)d_in[11];
    const float* bob  = (const float*)d_in[12];
    const float* bom  = (const float*)d_in[13];
    const float* bov  = (const float*)d_in[14];
    const float* f1w  = (const float*)d_in[15];
    const float* f1b  = (const float*)d_in[16];
    const float* f2w  = (const float*)d_in[17];
    const float* f2b  = (const float*)d_in[18];
    const float* dw   = (const float*)d_in[19];
    const float* db   = (const float*)d_in[20];

    float* out = (float*)d_out;
    float* recon = out;                                   // 32768*4*13*13
    float* mu    = out + (size_t)BTOT * 676;              // 32768*13*16
    float* lv    = mu  + (size_t)BTOT * 208;

    pack_kernel<<<1, 256>>>(iw, eps, w0, b0, w1, b1,
                            big, bib, bim, biv, bog, bob, bom, bov,
                            f1w, f1b, f2w, f2b, dw, db);

    void* stage_ptr = nullptr;
    cudaGetSymbolAddress(&stage_ptr, gStage);
    cudaMemcpyToSymbolAsync(cP, stage_ptr, sizeof(CParams), 0,
                            cudaMemcpyDeviceToDevice, 0);

    const int shmem = (int)sizeof(Smem);
    cudaFuncSetAttribute(vae_kernel, cudaFuncAttributeMaxDynamicSharedMemorySize, shmem);
    vae_kernel<<<BTOT / BLOC, NTHREADS, shmem>>>(adj, recon, mu, lv);
}

// round 9
// speedup vs baseline: 1.9416x; 1.1496x over previous
#include <cuda_runtime.h>
#include <cstddef>

#define BLOC 16
#define NTHREADS (BLOC * 13)   // 208
#define NB 13
#define DD 16
#define BTOT 32768

typedef unsigned long long u64;

// ---------------- packed constant parameter block ----------------
struct CParams {
    ulonglong2 iwq[NB][4];        // iw[m][d], d contiguous
    ulonglong2 w0q[4][DD][4];     // transposed [l][e][dquad]
    ulonglong2 w1q[4][DD][4];
    ulonglong2 dwq[4][DD][4];
    ulonglong2 fc1q[DD][4];
    ulonglong2 fc2q[DD][4];
    ulonglong2 b0q[4][4];
    ulonglong2 b1q[4][4];
    ulonglong2 dbq[4][4];
    ulonglong2 fc1bq[4];
    ulonglong2 fc2bq[4];
    float si[4][NB];
    float ti[4][NB];
    float so[4][NB];
    float to[4][NB];
    float fe[4];
};

__constant__ CParams cP;
__device__ CParams gStage;

// ---------------- pack kernel ----------------
__global__ void pack_kernel(
    const float* __restrict__ init_weight,
    const float* __restrict__ eps_param,
    const float* __restrict__ mlp_w0, const float* __restrict__ mlp_b0,
    const float* __restrict__ mlp_w1, const float* __restrict__ mlp_b1,
    const float* __restrict__ big, const float* __restrict__ bib,
    const float* __restrict__ bim, const float* __restrict__ biv,
    const float* __restrict__ bog, const float* __restrict__ bob,
    const float* __restrict__ bom, const float* __restrict__ bov,
    const float* __restrict__ fc1w, const float* __restrict__ fc1b,
    const float* __restrict__ fc2w, const float* __restrict__ fc2b,
    const float* __restrict__ decw, const float* __restrict__ decb)
{
    const int t = threadIdx.x;
    CParams* s = &gStage;

    for (int i = t; i < NB * DD; i += 256)
        ((float*)s->iwq)[i] = init_weight[i];

    for (int i = t; i < 4 * DD * DD; i += 256) {
        int d = i % DD;
        int e = (i / DD) % DD;
        int l = i / (DD * DD);
        ((float*)s->w0q)[i] = mlp_w0[l * 256 + d * DD + e];
        ((float*)s->w1q)[i] = mlp_w1[l * 256 + d * DD + e];
        ((float*)s->dwq)[i] = decw[l * 256 + d * DD + e];
    }
    for (int i = t; i < DD * DD; i += 256) {
        int d = i % DD;
        int e = i / DD;
        ((float*)s->fc1q)[i] = fc1w[d * DD + e];
        ((float*)s->fc2q)[i] = fc2w[d * DD + e];
    }
    if (t < 4 * DD) {
        ((float*)s->b0q)[t] = mlp_b0[t];
        ((float*)s->b1q)[t] = mlp_b1[t];
        ((float*)s->dbq)[t] = decb[t];
    }
    if (t < DD) {
        ((float*)s->fc1bq)[t] = fc1b[t];
        ((float*)s->fc2bq)[t] = fc2b[t];
    }
    if (t < 4 * NB) {
        float siv = big[t] * rsqrtf(biv[t] + 1e-5f);
        float sov = bog[t] * rsqrtf(bov[t] + 1e-5f);
        ((float*)s->si)[t] = siv;
        ((float*)s->ti)[t] = bib[t] - bim[t] * siv;
        ((float*)s->so)[t] = sov;
        ((float*)s->to)[t] = bob[t] - bom[t] * sov;
    }
    if (t < 4) s->fe[t] = 1.f + eps_param[t];
}

// ---------------- f32x2 helpers ----------------
__device__ __forceinline__ u64 pack2(float lo, float hi) {
    u64 r; asm("mov.b64 %0, {%1, %2};" : "=l"(r) : "f"(lo), "f"(hi)); return r;
}
__device__ __forceinline__ u64 bcast2(float v) {
    u64 r; asm("mov.b64 %0, {%1, %1};" : "=l"(r) : "f"(v)); return r;
}
__device__ __forceinline__ void unpack2(u64 v, float& lo, float& hi) {
    asm("mov.b64 {%0, %1}, %2;" : "=f"(lo), "=f"(hi) : "l"(v));
}
__device__ __forceinline__ u64 fma2(u64 a, u64 b, u64 c) {
    u64 r; asm("fma.rn.f32x2 %0, %1, %2, %3;" : "=l"(r) : "l"(a), "l"(b), "l"(c)); return r;
}
__device__ __forceinline__ u64 mul2(u64 a, u64 b) {
    u64 r; asm("mul.rn.f32x2 %0, %1, %2;" : "=l"(r) : "l"(a), "l"(b)); return r;
}

__device__ __forceinline__ float leaky(float v) {
    return v >= 0.f ? v : 0.01f * v;
}

__device__ __forceinline__ void mat16q(const ulonglong2 (*__restrict__ wq)[4],
                                       const ulonglong2* __restrict__ bq,
                                       const float* __restrict__ v,
                                       u64* __restrict__ out)
{
#pragma unroll
    for (int q = 0; q < 4; q++) {
        ulonglong2 bb = bq[q];
        out[2 * q] = bb.x;
        out[2 * q + 1] = bb.y;
    }
#pragma unroll
    for (int e = 0; e < DD; e++) {
        u64 ve = bcast2(v[e]);
#pragma unroll
        for (int q = 0; q < 4; q++) {
            ulonglong2 w = wq[e][q];
            out[2 * q]     = fma2(ve, w.x, out[2 * q]);
            out[2 * q + 1] = fma2(ve, w.y, out[2 * q + 1]);
        }
    }
}

// ---------------- main kernel ----------------
struct Smem {
    union {
        float4 adj[BLOC * 169];   // staging phase + layers: packed adj quads
        float recon[BLOC * 676];  // decoder phase: recon staging (exact same size)
    };
    float x[2][BLOC][NB][DD];     // ping-pong node features / temp / mu-lv staging
    float si[4 * NB], ti[4 * NB], so[4 * NB], to[4 * NB];
    float fe[4];
};                                 // ~70.7 KB -> 3 blocks/SM

#define STORE16(dst, src) do {                                  \
    float4* _p = (float4*)(dst);                                \
    _p[0] = make_float4((src)[0],(src)[1],(src)[2],(src)[3]);   \
    _p[1] = make_float4((src)[4],(src)[5],(src)[6],(src)[7]);   \
    _p[2] = make_float4((src)[8],(src)[9],(src)[10],(src)[11]); \
    _p[3] = make_float4((src)[12],(src)[13],(src)[14],(src)[15]);\
} while (0)

#define STOREP8(dst, src) do {                                  \
    ulonglong2* _p = (ulonglong2*)(dst);                        \
    _p[0] = make_ulonglong2((src)[0], (src)[1]);                \
    _p[1] = make_ulonglong2((src)[2], (src)[3]);                \
    _p[2] = make_ulonglong2((src)[4], (src)[5]);                \
    _p[3] = make_ulonglong2((src)[6], (src)[7]);                \
} while (0)

__global__ void __launch_bounds__(NTHREADS, 3) vae_kernel(
    const float* __restrict__ adj,
    float* __restrict__ out_recon,
    float* __restrict__ out_mu,
    float* __restrict__ out_logvar)
{
    extern __shared__ unsigned char smem_raw[];
    Smem* s = (Smem*)smem_raw;
    const int tid = threadIdx.x;

    // ---- stage adj with channel transpose: [i][n][m] -> [(n,m)][i] quad ----
    {
        const float* src = adj + (size_t)blockIdx.x * (BLOC * 676);
#pragma unroll 1
        for (int idx = tid; idx < BLOC * 169; idx += NTHREADS) {
            int bl = idx / 169;
            int nm = idx - bl * 169;
            const float* p = src + bl * 676 + nm;
            float4 q;
            q.x = p[0];
            q.y = p[169];
            q.z = p[338];
            q.w = p[507];
            s->adj[idx] = q;
        }
    }
    if (tid < 4 * NB) {
        s->si[tid] = ((const float*)gStage.si)[tid];
        s->ti[tid] = ((const float*)gStage.ti)[tid];
        s->so[tid] = ((const float*)gStage.so)[tid];
        s->to[tid] = ((const float*)gStage.to)[tid];
    }
    if (tid < 4) s->fe[tid] = gStage.fe[tid];
    __syncthreads();

    const int b_loc = tid / 13;
    const int n = tid - b_loc * 13;

    const float4* ab4 = s->adj + b_loc * 169 + n * 13;

    // ---- init: x[n][:] = sum_m (sum_i adj[i][n][m]) * iw[m][:] ----
    float xr[16];
    {
        u64 acc[8];
#pragma unroll
        for (int j = 0; j < 8; j++) acc[j] = 0ull;
#pragma unroll
        for (int m = 0; m < 13; m++) {
            float4 a = ab4[m];
            u64 a2 = bcast2((a.x + a.y) + (a.z + a.w));
#pragma unroll
            for (int q = 0; q < 4; q++) {
                ulonglong2 w = cP.iwq[m][q];
                acc[2 * q]     = fma2(a2, w.x, acc[2 * q]);
                acc[2 * q + 1] = fma2(a2, w.y, acc[2 * q + 1]);
            }
        }
        STOREP8(&s->x[0][b_loc][n][0], acc);
#pragma unroll
        for (int j = 0; j < 8; j++) unpack2(acc[j], xr[2 * j], xr[2 * j + 1]);
    }
    __syncthreads();

    // ---- 4 GIN layers (ping-pong x, ONE barrier per layer) ----
#pragma unroll 1
    for (int l = 0; l < 4; l++) {
        const int bnidx = l * 13 + n;
        const u64 si2 = bcast2(s->si[bnidx]);
        const u64 ti2 = bcast2(s->ti[bnidx]);
        const u64 so2 = bcast2(s->so[bnidx]);
        const u64 to2 = bcast2(s->to[bnidx]);
        const u64 fe2 = bcast2(s->fe[l]);

        const float* xbR = &s->x[l & 1][b_loc][0][0];

        u64 agg[8];
#pragma unroll
        for (int j = 0; j < 8; j++) agg[j] = mul2(fe2, pack2(xr[2 * j], xr[2 * j + 1]));
#pragma unroll
        for (int m = 0; m < 13; m++) {
            float4 a = ab4[m];
            const ulonglong2* xq = (const ulonglong2*)(xbR + m * 16);
            ulonglong2 x0 = xq[0], x1 = xq[1], x2 = xq[2], x3 = xq[3];
            u64 p0 = bcast2(a.x), p1 = bcast2(a.y), p2 = bcast2(a.z), p3 = bcast2(a.w);
            agg[0] = fma2(p0, x0.x, agg[0]);
            agg[1] = fma2(p0, x0.y, agg[1]);
            agg[2] = fma2(p1, x1.x, agg[2]);
            agg[3] = fma2(p1, x1.y, agg[3]);
            agg[4] = fma2(p2, x2.x, agg[4]);
            agg[5] = fma2(p2, x2.y, agg[5]);
            agg[6] = fma2(p3, x3.x, agg[6]);
            agg[7] = fma2(p3, x3.y, agg[7]);
        }
        float aggs[16];
#pragma unroll
        for (int j = 0; j < 8; j++) unpack2(agg[j], aggs[2 * j], aggs[2 * j + 1]);

        u64 h1p[8];
        mat16q(cP.w0q[l], cP.b0q[l], aggs, h1p);
        float h1[16];
#pragma unroll
        for (int j = 0; j < 8; j++) {
            u64 t = fma2(si2, h1p[j], ti2);
            float lo, hi; unpack2(t, lo, hi);
            h1[2 * j] = leaky(lo); h1[2 * j + 1] = leaky(hi);
        }
        u64 h2p[8];
        mat16q(cP.w1q[l], cP.b1q[l], h1, h2p);
#pragma unroll
        for (int j = 0; j < 8; j++) {
            u64 t = fma2(so2, h2p[j], to2);
            float lo, hi; unpack2(t, lo, hi);
            xr[2 * j] = leaky(lo); xr[2 * j + 1] = leaky(hi);
        }

        STORE16(&s->x[(l + 1) & 1][b_loc][n][0], xr);
        __syncthreads();
    }

    // ---- heads: mu / logvar -> stage in dead x buffers, coalesced copy out ----
    float muS[16];
    {
        u64 mup[8], lvp[8];
        mat16q(cP.fc1q, cP.fc1bq, xr, mup);
        mat16q(cP.fc2q, cP.fc2bq, xr, lvp);
        STOREP8(&s->x[0][b_loc][n][0], mup);   // x layout == mu layout
        STOREP8(&s->x[1][b_loc][n][0], lvp);
#pragma unroll
        for (int j = 0; j < 8; j++) unpack2(mup[j], muS[2 * j], muS[2 * j + 1]);
    }
    __syncthreads();
    {
        const float4* smu = (const float4*)&s->x[0][0][0][0];
        const float4* slv = (const float4*)&s->x[1][0][0][0];
        float4* dmu = (float4*)(out_mu + (size_t)blockIdx.x * (BLOC * 208));
        float4* dlv = (float4*)(out_logvar + (size_t)blockIdx.x * (BLOC * 208));
#pragma unroll 1
        for (int i = tid; i < (BLOC * 208) / 4; i += NTHREADS) {
            dmu[i] = smu[i];
            dlv[i] = slv[i];
        }
    }
    __syncthreads();   // x buffers free again for decoder temps

    // ---- decoder: temp in ping-pong x; recon into staging (adj is dead) ----
#pragma unroll 1
    for (int k = 0; k < 4; k++) {
        u64 t2[8];
        mat16q(cP.dwq[k], cP.dbq[k], muS, t2);
        STOREP8(&s->x[k & 1][b_loc][n][0], t2);
        __syncthreads();
        const float* tb = &s->x[k & 1][b_loc][0][0];
        float* ro = s->recon + b_loc * 676 + k * 169 + n * 13;
#pragma unroll
        for (int m = 0; m < 13; m++) {
            const ulonglong2* tq = (const ulonglong2*)(tb + m * 16);
            ulonglong2 q0 = tq[0], q1 = tq[1], q2 = tq[2], q3 = tq[3];
            u64 acc2 = mul2(t2[0], q0.x);
            acc2 = fma2(t2[1], q0.y, acc2);
            acc2 = fma2(t2[2], q1.x, acc2);
            acc2 = fma2(t2[3], q1.y, acc2);
            acc2 = fma2(t2[4], q2.x, acc2);
            acc2 = fma2(t2[5], q2.y, acc2);
            acc2 = fma2(t2[6], q3.x, acc2);
            acc2 = fma2(t2[7], q3.y, acc2);
            float lo, hi; unpack2(acc2, lo, hi);
            ro[m] = fmaxf(lo + hi, 0.f);
        }
        __syncthreads();   // recon rows of this k done before... (k+2 reuses x buffer)
    }

    // ---- coalesced recon writeback: 43.3 KB contiguous per block ----
    {
        const float4* srb = (const float4*)s->recon;
        float4* drb = (float4*)(out_recon + (size_t)blockIdx.x * (BLOC * 676));
#pragma unroll 1
        for (int i = tid; i < (BLOC * 676) / 4; i += NTHREADS)
            drb[i] = srb[i];
    }
}

extern "C" void kernel_launch(void* const* d_in, const int* in_sizes, int n_in,
                              void* d_out, int out_size)
{
    const float* adj  = (const float*)d_in[0];
    const float* iw   = (const float*)d_in[1];
    const float* eps  = (const float*)d_in[2];
    const float* w0   = (const float*)d_in[3];
    const float* b0   = (const float*)d_in[4];
    const float* w1   = (const float*)d_in[5];
    const float* b1   = (const float*)d_in[6];
    const float* big  = (const float*)d_in[7];
    const float* bib  = (const float*)d_in[8];
    const float* bim  = (const float*)d_in[9];
    const float* biv  = (const float*)d_in[10];
    const float* bog  = (const float*)d_in[11];
    const float* bob  = (const float*)d_in[12];
    const float* bom  = (const float*)d_in[13];
    const float* bov  = (const float*)d_in[14];
    const float* f1w  = (const float*)d_in[15];
    const float* f1b  = (const float*)d_in[16];
    const float* f2w  = (const float*)d_in[17];
    const float* f2b  = (const float*)d_in[18];
    const float* dw   = (const float*)d_in[19];
    const float* db   = (const float*)d_in[20];

    float* out = (float*)d_out;
    float* recon = out;                                   // 32768*4*13*13
    float* mu    = out + (size_t)BTOT * 676;              // 32768*13*16
    float* lv    = mu  + (size_t)BTOT * 208;

    pack_kernel<<<1, 256>>>(iw, eps, w0, b0, w1, b1,
                            big, bib, bim, biv, bog, bob, bom, bov,
                            f1w, f1b, f2w, f2b, dw, db);

    void* stage_ptr = nullptr;
    cudaGetSymbolAddress(&stage_ptr, gStage);
    cudaMemcpyToSymbolAsync(cP, stage_ptr, sizeof(CParams), 0,
                            cudaMemcpyDeviceToDevice, 0);

    const int shmem = (int)sizeof(Smem);
    cudaFuncSetAttribute(vae_kernel, cudaFuncAttributeMaxDynamicSharedMemorySize, shmem);
    vae_kernel<<<BTOT / BLOC, NTHREADS, shmem>>>(adj, recon, mu, lv);
}